// round 1
// baseline (speedup 1.0000x reference)
#include <cuda_runtime.h>
#include <math.h>

#define BN 4
#define CN 64
#define C2N 32
#define HN 48
#define WN 48
#define HWN 2304
#define LTOT 7470
#define LPAD 7472   // padded score stride (mult of 4 for float4 loads)

__constant__ int    c_HS[5]   = {48, 43, 38, 33, 28};
__constant__ int    c_LS[5]   = {2304, 1849, 1444, 1089, 784};
__constant__ int    c_LOFF[5] = {0, 2304, 4153, 5597, 6686};
__constant__ double c_SC[5]   = {1.0, 0.9, 0.8, 0.7, 0.6};

// ---------------- scratch (static device allocations) ----------------
__device__ float g_ref[(size_t)BN * CN * LTOT];    // resized pyramid (scale0 = x)
__device__ float g_m  [(size_t)BN * C2N * LTOT];   // prelu(w_m . ref)
__device__ float g_e  [(size_t)BN * CN * LTOT];    // prelu(w_a . ref)
__device__ float g_mb [(size_t)BN * C2N * HWN];    // match_base
__device__ float g_Q  [(size_t)BN * HWN * 288];
__device__ float g_K  [(size_t)BN * LTOT * 288];
__device__ float g_V  [(size_t)BN * LTOT * 576];
__device__ float g_S  [(size_t)BN * HWN * LPAD];   // scores -> attn (in place)
__device__ float g_Z  [(size_t)BN * HWN * 576];

// ---------------- bicubic weight (A = -0.75) ----------------
__device__ __forceinline__ float cubicw(float t) {
    const float A = -0.75f;
    if (t <= 1.f) return ((A + 2.f) * t - (A + 3.f)) * t * t + 1.f;
    if (t <  2.f) return (((t - 5.f) * t + 8.f) * t - 4.f) * A;
    return 0.f;
}

// ---------------- stage 0: copy x into pyramid scale 0 ----------------
__global__ void k_copy_ref0(const float* __restrict__ x) {
    int i = blockIdx.x * blockDim.x + threadIdx.x;
    if (i >= BN * CN * HWN) return;
    int b = i / (CN * HWN), r = i % (CN * HWN);
    g_ref[(size_t)b * CN * LTOT + r] = x[i];
}

// ---------------- stage 1: bicubic resize for scales 1..4 ----------------
__global__ void k_resize(const float* __restrict__ x) {
    int s  = blockIdx.y + 1;
    int hs = c_HS[s];
    int ls = hs * hs;
    int i  = blockIdx.x * blockDim.x + threadIdx.x;
    if (i >= BN * CN * ls) return;
    int b = i / (CN * ls), r = i % (CN * ls);
    int c = r / ls, p = r % ls;
    int oy = p / hs, ox = p % hs;
    double sc = c_SC[s];

    double syd = (oy + 0.5) / sc - 0.5;
    int   fy   = (int)floor(syd);
    float fry  = (float)(syd - fy);
    double sxd = (ox + 0.5) / sc - 0.5;
    int   fx   = (int)floor(sxd);
    float frx  = (float)(sxd - fx);

    float wy[4], wx[4];
    int   iy[4], ix[4];
#pragma unroll
    for (int k = 0; k < 4; k++) {
        wy[k] = cubicw(fabsf((float)(k - 1) - fry));
        int t = fy + k - 1; iy[k] = min(max(t, 0), HN - 1);
        wx[k] = cubicw(fabsf((float)(k - 1) - frx));
        t = fx + k - 1; ix[k] = min(max(t, 0), WN - 1);
    }
    const float* xp = x + ((size_t)b * CN + c) * HWN;
    float acc = 0.f;
#pragma unroll
    for (int ky = 0; ky < 4; ky++) {
        float ra = 0.f;
#pragma unroll
        for (int kx = 0; kx < 4; kx++) ra += wx[kx] * xp[iy[ky] * WN + ix[kx]];
        acc += wy[ky] * ra;
    }
    g_ref[(size_t)b * CN * LTOT + (size_t)c_LOFF[s] * CN + (size_t)c * ls + p] = acc;
}

// ---------------- stage 2: fused 1x1 convs (w_m -> 32ch, w_a -> 64ch) + PReLU ----------------
#define TPX 64
__global__ void k_conv_me(const float* __restrict__ w_m, const float* __restrict__ b_m,
                          const float* __restrict__ a_m, const float* __restrict__ w_a,
                          const float* __restrict__ b_a, const float* __restrict__ a_a) {
    int bs = blockIdx.y;
    int b = bs / 5, s = bs % 5;
    int ls = c_LS[s];
    int p0 = blockIdx.x * TPX;
    if (p0 >= ls) return;

    __shared__ float ws[96 * 64];
    __shared__ float bsm[96];
    __shared__ float intile[64][TPX];
    int tid = threadIdx.x;
    for (int i = tid; i < 32 * 64; i += 256) ws[i] = w_m[i];
    for (int i = tid; i < 64 * 64; i += 256) ws[32 * 64 + i] = w_a[i];
    if (tid < 32) bsm[tid] = b_m[tid];
    else if (tid < 96) bsm[tid] = b_a[tid - 32];
    float alm = *a_m, ala = *a_a;

    const float* inb = g_ref + (size_t)b * CN * LTOT + (size_t)c_LOFF[s] * CN;
    for (int i = tid; i < 64 * TPX; i += 256) {
        int c = i / TPX, p = i % TPX;
        intile[c][p] = (p0 + p < ls) ? inb[(size_t)c * ls + p0 + p] : 0.f;
    }
    __syncthreads();

    float* outm = g_m + (size_t)b * C2N * LTOT + (size_t)c_LOFF[s] * C2N;
    float* oute = g_e + (size_t)b * CN * LTOT + (size_t)c_LOFF[s] * CN;
#pragma unroll
    for (int j = 0; j < (96 * TPX) / 256; j++) {
        int pi = tid + 256 * j;
        int o = pi / TPX, p = pi % TPX;
        float acc = bsm[o];
        const float* wr = ws + o * 64;
#pragma unroll
        for (int c = 0; c < 64; c++) acc += wr[c] * intile[c][p];
        float al = (o < 32) ? alm : ala;
        float v = acc >= 0.f ? acc : al * acc;
        if (p0 + p < ls) {
            if (o < 32) outm[(size_t)o * ls + p0 + p] = v;
            else        oute[(size_t)(o - 32) * ls + p0 + p] = v;
        }
    }
}

__global__ void k_conv_mb(const float* __restrict__ x, const float* __restrict__ w,
                          const float* __restrict__ bias, const float* __restrict__ alpha) {
    int b = blockIdx.y;
    int p0 = blockIdx.x * TPX;
    __shared__ float ws[32 * 64];
    __shared__ float bsm[32];
    __shared__ float intile[64][TPX];
    int tid = threadIdx.x;
    for (int i = tid; i < 2048; i += 256) ws[i] = w[i];
    if (tid < 32) bsm[tid] = bias[tid];
    float al = *alpha;
    const float* inb = x + (size_t)b * CN * HWN;
    for (int i = tid; i < 64 * TPX; i += 256) {
        int c = i / TPX, p = i % TPX;
        intile[c][p] = inb[(size_t)c * HWN + p0 + p];
    }
    __syncthreads();
#pragma unroll
    for (int j = 0; j < (32 * TPX) / 256; j++) {
        int pi = tid + 256 * j;
        int o = pi / TPX, p = pi % TPX;
        float acc = bsm[o];
        const float* wr = ws + o * 64;
#pragma unroll
        for (int c = 0; c < 64; c++) acc += wr[c] * intile[c][p];
        g_mb[((size_t)b * C2N + o) * HWN + p0 + p] = acc >= 0.f ? acc : al * acc;
    }
}

// ---------------- stage 3: im2col Q / K(normalized) / V ----------------
__global__ void k_im2col_q() {
    int bq = blockIdx.x;
    int b = bq / HWN, q = bq % HWN;
    int j = threadIdx.x;          // 288
    int c = j / 9, u = (j % 9) / 3, v = j % 3;
    int h = q / WN, w = q % WN;
    int hh = h + u - 1, ww = w + v - 1;
    float val = 0.f;
    if (hh >= 0 && hh < HN && ww >= 0 && ww < WN)
        val = g_mb[((size_t)b * C2N + c) * HWN + hh * WN + ww];
    g_Q[((size_t)b * HWN + q) * 288 + j] = val;
}

__global__ void k_im2col_k(const float* __restrict__ eps_p) {
    int bl = blockIdx.x;
    int b = bl / LTOT, l = bl % LTOT;
    int s = 0;
#pragma unroll
    for (int t = 1; t < 5; t++) if (l >= c_LOFF[t]) s = t;
    int hs = c_HS[s], ls = c_LS[s];
    int p = l - c_LOFF[s];
    int y = p / hs, xx = p % hs;
    int j = threadIdx.x;          // 288
    int c = j / 9, u = (j % 9) / 3, v = j % 3;
    int yy = y + u - 1, x2 = xx + v - 1;
    float val = 0.f;
    if (yy >= 0 && yy < hs && x2 >= 0 && x2 < hs)
        val = g_m[(size_t)b * C2N * LTOT + (size_t)c_LOFF[s] * C2N + (size_t)c * ls + yy * hs + x2];

    __shared__ float red[512];
    red[j] = val * val;
    if (j < 224) red[288 + j] = 0.f;
    __syncthreads();
    for (int st = 256; st > 0; st >>= 1) {
        if (j < st) red[j] += red[j + st];
        __syncthreads();
    }
    float inv = 1.f / fmaxf(sqrtf(red[0]), *eps_p);
    g_K[((size_t)b * LTOT + l) * 288 + j] = val * inv;
}

__global__ void k_im2col_v() {
    int bl = blockIdx.x;
    int b = bl / LTOT, l = bl % LTOT;
    int s = 0;
#pragma unroll
    for (int t = 1; t < 5; t++) if (l >= c_LOFF[t]) s = t;
    int hs = c_HS[s], ls = c_LS[s];
    int p = l - c_LOFF[s];
    int y = p / hs, xx = p % hs;
    int j = threadIdx.x;          // 576
    int c = j / 9, u = (j % 9) / 3, v = j % 3;
    int yy = y + u - 1, x2 = xx + v - 1;
    float val = 0.f;
    if (yy >= 0 && yy < hs && x2 >= 0 && x2 < hs)
        val = g_e[(size_t)b * CN * LTOT + (size_t)c_LOFF[s] * CN + (size_t)c * ls + yy * hs + x2];
    g_V[((size_t)b * LTOT + l) * 576 + j] = val;
}

// ---------------- stage 4/6: 128x128x16 fp32 GEMM, 8x8 microtiles ----------------
// BISNT=true : C[M,N] = A[M,K] * B[N,K]^T   (both K-inner row-major)
// BISNT=false: C[M,N] = A[M,K] * B[K,N]     (both row-major)
template <bool BISNT>
__device__ __forceinline__ void gemm_dev(const float* __restrict__ A,
                                         const float* __restrict__ B,
                                         float* __restrict__ C,
                                         int M, int N, int Kd,
                                         int lda, int ldb, int ldc) {
    __shared__ float As[128][20];   // row-major [m][k], pad 20 (broadcast a-frag reads)
    __shared__ float Bs[16][132];   // [k][n], pad 132 (float4 b-frag reads)
    int tid = threadIdx.x;          // 256
    int tx = tid % 16, ty = tid / 16;
    int m0 = blockIdx.y * 128, n0 = blockIdx.x * 128;

    float acc[8][8];
#pragma unroll
    for (int i = 0; i < 8; i++)
#pragma unroll
        for (int j = 0; j < 8; j++) acc[i][j] = 0.f;

    for (int k0 = 0; k0 < Kd; k0 += 16) {
        // --- load A tile (float4 along K) ---
#pragma unroll
        for (int it = 0; it < 2; it++) {
            int rr = tid / 4 + 64 * it;
            int kq = (tid % 4) * 4;
            float4 va = make_float4(0.f, 0.f, 0.f, 0.f);
            int gr = m0 + rr;
            if (gr < M) {
                int gk = k0 + kq;
                if (gk + 3 < Kd) {
                    va = *(const float4*)(A + (size_t)gr * lda + gk);
                } else {
                    float t0 = (gk + 0 < Kd) ? A[(size_t)gr * lda + gk + 0] : 0.f;
                    float t1 = (gk + 1 < Kd) ? A[(size_t)gr * lda + gk + 1] : 0.f;
                    float t2 = (gk + 2 < Kd) ? A[(size_t)gr * lda + gk + 2] : 0.f;
                    float t3 = (gk + 3 < Kd) ? A[(size_t)gr * lda + gk + 3] : 0.f;
                    va = make_float4(t0, t1, t2, t3);
                }
            }
            *(float4*)&As[rr][kq] = va;
        }
        // --- load B tile ---
        if (BISNT) {
#pragma unroll
            for (int it = 0; it < 2; it++) {
                int nn = tid / 4 + 64 * it;
                int kq = (tid % 4) * 4;
                float4 vb = make_float4(0.f, 0.f, 0.f, 0.f);
                int gn = n0 + nn;
                if (gn < N) {
                    int gk = k0 + kq;
                    if (gk + 3 < Kd) {
                        vb = *(const float4*)(B + (size_t)gn * ldb + gk);
                    } else {
                        float t0 = (gk + 0 < Kd) ? B[(size_t)gn * ldb + gk + 0] : 0.f;
                        float t1 = (gk + 1 < Kd) ? B[(size_t)gn * ldb + gk + 1] : 0.f;
                        float t2 = (gk + 2 < Kd) ? B[(size_t)gn * ldb + gk + 2] : 0.f;
                        float t3 = (gk + 3 < Kd) ? B[(size_t)gn * ldb + gk + 3] : 0.f;
                        vb = make_float4(t0, t1, t2, t3);
                    }
                }
                Bs[kq + 0][nn] = vb.x;
                Bs[kq + 1][nn] = vb.y;
                Bs[kq + 2][nn] = vb.z;
                Bs[kq + 3][nn] = vb.w;
            }
        } else {
#pragma unroll
            for (int it = 0; it < 2; it++) {
                int kk = tid / 32 + 8 * it;
                int nn = (tid % 32) * 4;
                float4 vb = make_float4(0.f, 0.f, 0.f, 0.f);
                int gk = k0 + kk;
                if (gk < Kd) {
                    int gn = n0 + nn;
                    if (gn + 3 < N) {
                        vb = *(const float4*)(B + (size_t)gk * ldb + gn);
                    } else {
                        float t0 = (gn + 0 < N) ? B[(size_t)gk * ldb + gn + 0] : 0.f;
                        float t1 = (gn + 1 < N) ? B[(size_t)gk * ldb + gn + 1] : 0.f;
                        float t2 = (gn + 2 < N) ? B[(size_t)gk * ldb + gn + 2] : 0.f;
                        float t3 = (gn + 3 < N) ? B[(size_t)gk * ldb + gn + 3] : 0.f;
                        vb = make_float4(t0, t1, t2, t3);
                    }
                }
                *(float4*)&Bs[kk][nn] = vb;
            }
        }
        __syncthreads();
        // --- compute ---
#pragma unroll
        for (int kk = 0; kk < 16; kk++) {
            float a[8];
#pragma unroll
            for (int i = 0; i < 8; i++) a[i] = As[ty * 8 + i][kk];
            float4 b0 = *(const float4*)&Bs[kk][tx * 8];
            float4 b1 = *(const float4*)&Bs[kk][tx * 8 + 4];
            float bb[8] = {b0.x, b0.y, b0.z, b0.w, b1.x, b1.y, b1.z, b1.w};
#pragma unroll
            for (int i = 0; i < 8; i++)
#pragma unroll
                for (int j = 0; j < 8; j++) acc[i][j] += a[i] * bb[j];
        }
        __syncthreads();
    }
    // --- store ---
#pragma unroll
    for (int i = 0; i < 8; i++) {
        int gr = m0 + ty * 8 + i;
        if (gr < M) {
#pragma unroll
            for (int j = 0; j < 8; j++) {
                int gn = n0 + tx * 8 + j;
                if (gn < N) C[(size_t)gr * ldc + gn] = acc[i][j];
            }
        }
    }
}

__global__ __launch_bounds__(256) void k_gemm_qk() {
    int b = blockIdx.z;
    gemm_dev<true>(g_Q + (size_t)b * HWN * 288,
                   g_K + (size_t)b * LTOT * 288,
                   g_S + (size_t)b * HWN * LPAD,
                   HWN, LTOT, 288, 288, 288, LPAD);
}

__global__ __launch_bounds__(256) void k_gemm_av() {
    int b = blockIdx.z;
    gemm_dev<false>(g_S + (size_t)b * HWN * LPAD,
                    g_V + (size_t)b * LTOT * 576,
                    g_Z + (size_t)b * HWN * 576,
                    HWN, 576, LTOT, LPAD, 576, 576);
}

// ---------------- stage 5: softmax over L (row-cached in registers) ----------------
__global__ __launch_bounds__(256) void k_softmax() {
    size_t row = blockIdx.x;                  // b*HWN + q
    float* ptr = g_S + row * LPAD;
    int tid = threadIdx.x;
    float v[30];
    float mx = -1e30f;
#pragma unroll
    for (int i = 0; i < 30; i++) {
        int idx = tid + i * 256;
        v[i] = (idx < LTOT) ? ptr[idx] : -1e30f;
        mx = fmaxf(mx, v[i]);
    }
    __shared__ float red[256];
    red[tid] = mx;
    __syncthreads();
    for (int st = 128; st > 0; st >>= 1) {
        if (tid < st) red[tid] = fmaxf(red[tid], red[tid + st]);
        __syncthreads();
    }
    mx = red[0];
    __syncthreads();
    float sum = 0.f;
#pragma unroll
    for (int i = 0; i < 30; i++) {
        int idx = tid + i * 256;
        if (idx < LTOT) {
            v[i] = __expf(10.f * (v[i] - mx));
            sum += v[i];
        }
    }
    red[tid] = sum;
    __syncthreads();
    for (int st = 128; st > 0; st >>= 1) {
        if (tid < st) red[tid] += red[tid + st];
        __syncthreads();
    }
    float inv = 1.f / red[0];
#pragma unroll
    for (int i = 0; i < 30; i++) {
        int idx = tid + i * 256;
        if (idx < LTOT) ptr[idx] = v[i] * inv;
    }
}

// ---------------- stage 7: transposed-conv combine + residual ----------------
__global__ void k_combine(const float* __restrict__ x, float* __restrict__ out) {
    int i = blockIdx.x * blockDim.x + threadIdx.x;
    if (i >= BN * CN * HWN) return;
    int b = i / (CN * HWN), r = i % (CN * HWN);
    int c = r / HWN, p = r % HWN;
    int h = p / WN, w = p % WN;
    float acc = 0.f;
#pragma unroll
    for (int u = 0; u < 3; u++) {
        int hq = h + 1 - u;
        if (hq < 0 || hq >= HN) continue;
#pragma unroll
        for (int v = 0; v < 3; v++) {
            int wq = w + 1 - v;
            if (wq < 0 || wq >= WN) continue;
            acc += g_Z[((size_t)b * HWN + hq * WN + wq) * 576 + c * 9 + u * 3 + v];
        }
    }
    out[i] = x[i] + 0.25f * acc;
}

// ---------------- launch ----------------
extern "C" void kernel_launch(void* const* d_in, const int* in_sizes, int n_in,
                              void* d_out, int out_size) {
    const float* x    = (const float*)d_in[0];
    const float* w_mb = (const float*)d_in[1];
    const float* b_mb = (const float*)d_in[2];
    const float* a_mb = (const float*)d_in[3];
    const float* w_m  = (const float*)d_in[4];
    const float* b_m  = (const float*)d_in[5];
    const float* a_m  = (const float*)d_in[6];
    const float* w_a  = (const float*)d_in[7];
    const float* b_a  = (const float*)d_in[8];
    const float* a_a  = (const float*)d_in[9];
    const float* eps  = (const float*)d_in[10];
    float* out = (float*)d_out;

    k_copy_ref0<<<(BN * CN * HWN + 255) / 256, 256>>>(x);
    k_resize<<<dim3(1849, 4), 256>>>(x);                 // covers BN*CN*max(Ls>=1)=473344
    k_conv_me<<<dim3(36, BN * 5), 256>>>(w_m, b_m, a_m, w_a, b_a, a_a);
    k_conv_mb<<<dim3(36, BN), 256>>>(x, w_mb, b_mb, a_mb);
    k_im2col_q<<<BN * HWN, 288>>>();
    k_im2col_k<<<BN * LTOT, 288>>>(eps);
    k_im2col_v<<<BN * LTOT, 576>>>();
    k_gemm_qk<<<dim3((LTOT + 127) / 128, HWN / 128, BN), 256>>>();
    k_softmax<<<BN * HWN, 256>>>();
    k_gemm_av<<<dim3((576 + 127) / 128, HWN / 128, BN), 256>>>();
    k_combine<<<(BN * CN * HWN + 255) / 256, 256>>>(x, out);
}

// round 5
// speedup vs baseline: 4.3004x; 4.3004x over previous
#include <cuda_runtime.h>
#include <cuda_fp16.h>
#include <math.h>
#include <stdint.h>

#define BN 4
#define CN 64
#define C2N 32
#define HN 48
#define WN 48
#define HWN 2304
#define LTOT 7470
#define KC1 864          // QK gemm K (3 x 288)
#define SPAD 7680        // score col stride
#define LP2 7488         // padded L for AV gemm

__constant__ int    c_HS[5]   = {48, 43, 38, 33, 28};
__constant__ int    c_LS[5]   = {2304, 1849, 1444, 1089, 784};
__constant__ int    c_LOFF[5] = {0, 2304, 4153, 5597, 6686};
__constant__ double c_SC[5]   = {1.0, 0.9, 0.8, 0.7, 0.6};

// ---------------- scratch ----------------
__device__ float g_ref[(size_t)BN * CN * LTOT];
__device__ float g_m  [(size_t)BN * C2N * LTOT];
__device__ float g_e  [(size_t)BN * CN * LTOT];
__device__ float g_mb [(size_t)BN * C2N * HWN];
__device__ __align__(16) __half g_Qc [(size_t)BN * HWN * KC1];   // [Qh|Qh|Ql]
__device__ __align__(16) __half g_Kc [(size_t)BN * LTOT * KC1];  // [Kh|Kl|Kh]
__device__ __align__(16) __half g_V16[(size_t)BN * 576 * LP2];   // V^T fp16
__device__ __align__(16) __half g_A16[(size_t)BN * HWN * LP2];   // attn fp16
__device__ __align__(16) float g_S[(size_t)BN * HWN * SPAD];     // raw scores fp32
__device__ __align__(16) float g_Z[(size_t)BN * HWN * 576];

// ---------------- ptx helpers ----------------
__device__ __forceinline__ uint32_t smem_u32(const void* p) {
    uint32_t a;
    asm("{ .reg .u64 t; cvta.to.shared.u64 t, %1; cvt.u32.u64 %0, t; }" : "=r"(a) : "l"(p));
    return a;
}
__device__ __forceinline__ void cp16(uint32_t d, const void* s, int sz) {
    asm volatile("cp.async.cg.shared.global [%0], [%1], 16, %2;"
                 :: "r"(d), "l"(s), "r"(sz) : "memory");
}
__device__ __forceinline__ void cp_commit() {
    asm volatile("cp.async.commit_group;" ::: "memory");
}
template <int N_>
__device__ __forceinline__ void cp_wait() {
    asm volatile("cp.async.wait_group %0;" :: "n"(N_) : "memory");
}
__device__ __forceinline__ void ldsm4(uint32_t* r, uint32_t addr) {
    asm volatile("ldmatrix.sync.aligned.m8n8.x4.shared.b16 {%0,%1,%2,%3}, [%4];"
        : "=r"(r[0]), "=r"(r[1]), "=r"(r[2]), "=r"(r[3]) : "r"(addr));
}
__device__ __forceinline__ void mma16816(float* c, const uint32_t* a, uint32_t b0, uint32_t b1) {
    asm volatile("mma.sync.aligned.m16n8k16.row.col.f32.f16.f16.f32 "
        "{%0,%1,%2,%3}, {%4,%5,%6,%7}, {%8,%9}, {%0,%1,%2,%3};"
        : "+f"(c[0]), "+f"(c[1]), "+f"(c[2]), "+f"(c[3])
        : "r"(a[0]), "r"(a[1]), "r"(a[2]), "r"(a[3]), "r"(b0), "r"(b1));
}
__device__ __forceinline__ void split_h(float v, __half& h, __half& l) {
    h = __float2half_rn(v);
    l = __float2half_rn(v - __half2float(h));
}

// ---------------- bicubic ----------------
__device__ __forceinline__ float cubicw(float t) {
    const float A = -0.75f;
    if (t <= 1.f) return ((A + 2.f) * t - (A + 3.f)) * t * t + 1.f;
    if (t <  2.f) return (((t - 5.f) * t + 8.f) * t - 4.f) * A;
    return 0.f;
}

__global__ void k_copy_ref0(const float* __restrict__ x) {
    int i = blockIdx.x * blockDim.x + threadIdx.x;
    if (i >= BN * CN * HWN) return;
    int b = i / (CN * HWN), r = i % (CN * HWN);
    g_ref[(size_t)b * CN * LTOT + r] = x[i];
}

__global__ void k_resize(const float* __restrict__ x) {
    int s  = blockIdx.y + 1;
    int hs = c_HS[s];
    int ls = hs * hs;
    int i  = blockIdx.x * blockDim.x + threadIdx.x;
    if (i >= BN * CN * ls) return;
    int b = i / (CN * ls), r = i % (CN * ls);
    int c = r / ls, p = r % ls;
    int oy = p / hs, ox = p % hs;
    double sc = c_SC[s];
    double syd = (oy + 0.5) / sc - 0.5;
    int   fy = (int)floor(syd);
    float fry = (float)(syd - fy);
    double sxd = (ox + 0.5) / sc - 0.5;
    int   fx = (int)floor(sxd);
    float frx = (float)(sxd - fx);
    float wy[4], wx[4]; int iy[4], ix[4];
#pragma unroll
    for (int k = 0; k < 4; k++) {
        wy[k] = cubicw(fabsf((float)(k - 1) - fry));
        int t = fy + k - 1; iy[k] = min(max(t, 0), HN - 1);
        wx[k] = cubicw(fabsf((float)(k - 1) - frx));
        t = fx + k - 1; ix[k] = min(max(t, 0), WN - 1);
    }
    const float* xp = x + ((size_t)b * CN + c) * HWN;
    float acc = 0.f;
#pragma unroll
    for (int ky = 0; ky < 4; ky++) {
        float ra = 0.f;
#pragma unroll
        for (int kx = 0; kx < 4; kx++) ra += wx[kx] * xp[iy[ky] * WN + ix[kx]];
        acc += wy[ky] * ra;
    }
    g_ref[(size_t)b * CN * LTOT + (size_t)c_LOFF[s] * CN + (size_t)c * ls + p] = acc;
}

// ---------------- 1x1 convs + PReLU ----------------
#define TPX 64
__global__ void k_conv_me(const float* __restrict__ w_m, const float* __restrict__ b_m,
                          const float* __restrict__ a_m, const float* __restrict__ w_a,
                          const float* __restrict__ b_a, const float* __restrict__ a_a) {
    int bs = blockIdx.y;
    int b = bs / 5, s = bs % 5;
    int ls = c_LS[s];
    int p0 = blockIdx.x * TPX;
    if (p0 >= ls) return;
    __shared__ float ws[96 * 64];
    __shared__ float bsm[96];
    __shared__ float intile[64][TPX];
    int tid = threadIdx.x;
    for (int i = tid; i < 32 * 64; i += 256) ws[i] = w_m[i];
    for (int i = tid; i < 64 * 64; i += 256) ws[32 * 64 + i] = w_a[i];
    if (tid < 32) bsm[tid] = b_m[tid];
    else if (tid < 96) bsm[tid] = b_a[tid - 32];
    float alm = *a_m, ala = *a_a;
    const float* inb = g_ref + (size_t)b * CN * LTOT + (size_t)c_LOFF[s] * CN;
    for (int i = tid; i < 64 * TPX; i += 256) {
        int c = i / TPX, p = i % TPX;
        intile[c][p] = (p0 + p < ls) ? inb[(size_t)c * ls + p0 + p] : 0.f;
    }
    __syncthreads();
    float* outm = g_m + (size_t)b * C2N * LTOT + (size_t)c_LOFF[s] * C2N;
    float* oute = g_e + (size_t)b * CN * LTOT + (size_t)c_LOFF[s] * CN;
#pragma unroll
    for (int j = 0; j < (96 * TPX) / 256; j++) {
        int pi = tid + 256 * j;
        int o = pi / TPX, p = pi % TPX;
        float acc = bsm[o];
        const float* wr = ws + o * 64;
#pragma unroll
        for (int c = 0; c < 64; c++) acc += wr[c] * intile[c][p];
        float al = (o < 32) ? alm : ala;
        float v = acc >= 0.f ? acc : al * acc;
        if (p0 + p < ls) {
            if (o < 32) outm[(size_t)o * ls + p0 + p] = v;
            else        oute[(size_t)(o - 32) * ls + p0 + p] = v;
        }
    }
}

__global__ void k_conv_mb(const float* __restrict__ x, const float* __restrict__ w,
                          const float* __restrict__ bias, const float* __restrict__ alpha) {
    int b = blockIdx.y;
    int p0 = blockIdx.x * TPX;
    __shared__ float ws[32 * 64];
    __shared__ float bsm[32];
    __shared__ float intile[64][TPX];
    int tid = threadIdx.x;
    for (int i = tid; i < 2048; i += 256) ws[i] = w[i];
    if (tid < 32) bsm[tid] = bias[tid];
    float al = *alpha;
    const float* inb = x + (size_t)b * CN * HWN;
    for (int i = tid; i < 64 * TPX; i += 256) {
        int c = i / TPX, p = i % TPX;
        intile[c][p] = inb[(size_t)c * HWN + p0 + p];
    }
    __syncthreads();
#pragma unroll
    for (int j = 0; j < (32 * TPX) / 256; j++) {
        int pi = tid + 256 * j;
        int o = pi / TPX, p = pi % TPX;
        float acc = bsm[o];
        const float* wr = ws + o * 64;
#pragma unroll
        for (int c = 0; c < 64; c++) acc += wr[c] * intile[c][p];
        g_mb[((size_t)b * C2N + o) * HWN + p0 + p] = acc >= 0.f ? acc : al * acc;
    }
}

// ---------------- builders ----------------
__global__ void k_build_q() {
    int bq = blockIdx.x;
    int b = bq / HWN, q = bq % HWN;
    int j = threadIdx.x;          // 288
    int c = j / 9, u = (j % 9) / 3, v = j % 3;
    int h = q / WN, w = q % WN;
    int hh = h + u - 1, ww = w + v - 1;
    float val = 0.f;
    if (hh >= 0 && hh < HN && ww >= 0 && ww < WN)
        val = g_mb[((size_t)b * C2N + c) * HWN + hh * WN + ww];
    __half hi, lo;
    split_h(val, hi, lo);
    size_t base = ((size_t)b * HWN + q) * KC1;
    g_Qc[base + j]       = hi;
    g_Qc[base + 288 + j] = hi;
    g_Qc[base + 576 + j] = lo;
}

__global__ void k_build_k(const float* __restrict__ eps_p) {
    int bl = blockIdx.x;
    int b = bl / LTOT, l = bl % LTOT;
    int s = 0;
#pragma unroll
    for (int t = 1; t < 5; t++) if (l >= c_LOFF[t]) s = t;
    int hs = c_HS[s], ls = c_LS[s];
    int p = l - c_LOFF[s];
    int y = p / hs, xx = p % hs;
    int j = threadIdx.x;          // 288
    int c = j / 9, u = (j % 9) / 3, v = j % 3;
    int yy = y + u - 1, x2 = xx + v - 1;
    float val = 0.f;
    if (yy >= 0 && yy < hs && x2 >= 0 && x2 < hs)
        val = g_m[(size_t)b * C2N * LTOT + (size_t)c_LOFF[s] * C2N + (size_t)c * ls + yy * hs + x2];
    __shared__ float red[512];
    red[j] = val * val;
    if (j < 224) red[288 + j] = 0.f;
    __syncthreads();
    for (int st = 256; st > 0; st >>= 1) {
        if (j < st) red[j] += red[j + st];
        __syncthreads();
    }
    float inv = 1.f / fmaxf(sqrtf(red[0]), *eps_p);
    __half hi, lo;
    split_h(val * inv, hi, lo);
    size_t base = ((size_t)b * LTOT + l) * KC1;
    g_Kc[base + j]       = hi;
    g_Kc[base + 288 + j] = lo;
    g_Kc[base + 576 + j] = hi;
}

__global__ void k_build_vt() {
    int j = blockIdx.x;           // 0..575 (channel-tap)
    int b = blockIdx.y;
    int c = j / 9, u = (j % 9) / 3, v = j % 3;
    size_t obase = ((size_t)b * 576 + j) * LP2;
    for (int l = threadIdx.x; l < LP2; l += blockDim.x) {
        float val = 0.f;
        if (l < LTOT) {
            int s = 0;
            if (l >= c_LOFF[4]) s = 4;
            else if (l >= c_LOFF[3]) s = 3;
            else if (l >= c_LOFF[2]) s = 2;
            else if (l >= c_LOFF[1]) s = 1;
            int hs = c_HS[s], ls = c_LS[s];
            int p = l - c_LOFF[s];
            int y = p / hs, xx = p % hs;
            int yy = y + u - 1, x2 = xx + v - 1;
            if (yy >= 0 && yy < hs && x2 >= 0 && x2 < hs)
                val = g_e[(size_t)b * CN * LTOT + (size_t)c_LOFF[s] * CN + (size_t)c * ls + yy * hs + x2];
        }
        g_V16[obase + l] = __float2half_rn(val);
    }
}

// ---------------- HMMA GEMM: C[M,N] = A[M,K] * B[N,K]^T ----------------
// block 128x128x32, 8 warps (warp tile 64x32), double-buffered cp.async,
// 80B-padded smem rows, ldmatrix.x4 for both operands, fp32 accum.
__device__ __forceinline__ void hgemm_dev(const __half* __restrict__ A,
                                          const __half* __restrict__ B,
                                          float* __restrict__ C,
                                          int N, int K, int lda, int ldb, int ldc) {
    __shared__ __align__(16) __half As[2][5120];   // 128 rows x 40 halves
    __shared__ __align__(16) __half Bs[2][5120];
    int tid = threadIdx.x, lane = tid & 31, w = tid >> 5;
    int wm = w >> 2, wn = w & 3;                  // warp grid 2(M) x 4(N)
    int m0 = blockIdx.y * 128, n0 = blockIdx.x * 128;

    const __half* Ab = A + (size_t)m0 * lda;
    uint32_t asm0 = smem_u32(&As[0][0]);
    uint32_t bsm0 = smem_u32(&Bs[0][0]);

    float c[4][4][4];
#pragma unroll
    for (int i = 0; i < 4; i++)
#pragma unroll
        for (int j = 0; j < 4; j++)
#pragma unroll
            for (int q = 0; q < 4; q++) c[i][j][q] = 0.f;

    int r = tid >> 2, g = tid & 3;     // load row / 16B-group
    int NC = K >> 5;

    auto issue = [&](int ch, int buf) {
        int k0 = ch << 5;
        uint32_t ab = asm0 + buf * 10240;
        uint32_t bb = bsm0 + buf * 10240;
#pragma unroll
        for (int it = 0; it < 2; ++it) {
            int rr = r + it * 64;
            cp16(ab + rr * 80 + g * 16, Ab + (size_t)rr * lda + k0 + g * 8, 16);
            int n = n0 + rr;
            cp16(bb + rr * 80 + g * 16, B + (size_t)n * ldb + k0 + g * 8,
                 (n < N) ? 16 : 0);
        }
        cp_commit();
    };

    issue(0, 0);
    for (int ch = 0; ch < NC; ++ch) {
        int buf = ch & 1;
        if (ch + 1 < NC) { issue(ch + 1, buf ^ 1); cp_wait<1>(); }
        else             { cp_wait<0>(); }
        __syncthreads();

        uint32_t abase = asm0 + buf * 10240;
        uint32_t bbase = bsm0 + buf * 10240;
        int lr = lane & 15, lh = lane >> 4;
#pragma unroll
        for (int ks = 0; ks < 2; ++ks) {
            uint32_t af[4][4], bf[2][4];
#pragma unroll
            for (int ms = 0; ms < 4; ++ms)
                ldsm4(af[ms], abase + (wm * 64 + ms * 16 + lr) * 80 + ks * 32 + lh * 16);
#pragma unroll
            for (int ns = 0; ns < 2; ++ns)
                ldsm4(bf[ns], bbase + (wn * 32 + ns * 16 + lr) * 80 + ks * 32 + lh * 16);
#pragma unroll
            for (int ms = 0; ms < 4; ++ms)
#pragma unroll
                for (int j = 0; j < 4; ++j)
                    mma16816(c[ms][j], af[ms], bf[j >> 1][j & 1], bf[j >> 1][2 + (j & 1)]);
        }
        __syncthreads();
    }

    // epilogue
#pragma unroll
    for (int ms = 0; ms < 4; ++ms) {
#pragma unroll
        for (int j = 0; j < 4; ++j) {
            int row = m0 + wm * 64 + ms * 16 + (lane >> 2);
            int col = n0 + wn * 32 + j * 8 + 2 * (lane & 3);
            if (col < N) {
                *(float2*)&C[(size_t)row * ldc + col] = make_float2(c[ms][j][0], c[ms][j][1]);
                *(float2*)&C[(size_t)(row + 8) * ldc + col] = make_float2(c[ms][j][2], c[ms][j][3]);
            }
        }
    }
}

__global__ __launch_bounds__(256) void k_gemm_qk() {
    int b = blockIdx.z;
    hgemm_dev(g_Qc + (size_t)b * HWN * KC1,
              g_Kc + (size_t)b * LTOT * KC1,
              g_S  + (size_t)b * HWN * SPAD,
              LTOT, KC1, KC1, KC1, SPAD);
}

__global__ __launch_bounds__(256) void k_gemm_av() {
    int b = blockIdx.z;
    hgemm_dev(g_A16 + (size_t)b * HWN * LP2,
              g_V16 + (size_t)b * 576 * LP2,
              g_Z   + (size_t)b * HWN * 576,
              576, LP2, LP2, LP2, 576);
}

// ---------------- softmax: S -> fp16 attn ----------------
__global__ __launch_bounds__(256) void k_softmax() {
    size_t row = blockIdx.x;
    const float* ptr = g_S + row * SPAD;
    __half* op = g_A16 + row * LP2;
    int tid = threadIdx.x;
    float v[30];
    float mx = -1e30f;
#pragma unroll
    for (int i = 0; i < 30; i++) {
        int idx = tid + i * 256;
        v[i] = (idx < LTOT) ? ptr[idx] : -1e30f;
        mx = fmaxf(mx, v[i]);
    }
    __shared__ float red[256];
    red[tid] = mx;
    __syncthreads();
    for (int st = 128; st > 0; st >>= 1) {
        if (tid < st) red[tid] = fmaxf(red[tid], red[tid + st]);
        __syncthreads();
    }
    mx = red[0];
    __syncthreads();
    float sum = 0.f;
#pragma unroll
    for (int i = 0; i < 30; i++) {
        int idx = tid + i * 256;
        if (idx < LTOT) {
            v[i] = __expf(10.f * (v[i] - mx));
            sum += v[i];
        }
    }
    red[tid] = sum;
    __syncthreads();
    for (int st = 128; st > 0; st >>= 1) {
        if (tid < st) red[tid] += red[tid + st];
        __syncthreads();
    }
    float inv = 1.f / red[0];
#pragma unroll
    for (int i = 0; i < 30; i++) {
        int idx = tid + i * 256;
        if (idx < LTOT) op[idx] = __float2half_rn(v[i] * inv);
        else if (idx < LP2) op[idx] = __float2half_rn(0.f);
    }
}

// ---------------- combine ----------------
__global__ void k_combine(const float* __restrict__ x, float* __restrict__ out) {
    int i = blockIdx.x * blockDim.x + threadIdx.x;
    if (i >= BN * CN * HWN) return;
    int b = i / (CN * HWN), r = i % (CN * HWN);
    int c = r / HWN, p = r % HWN;
    int h = p / WN, w = p % WN;
    float acc = 0.f;
#pragma unroll
    for (int u = 0; u < 3; u++) {
        int hq = h + 1 - u;
        if (hq < 0 || hq >= HN) continue;
#pragma unroll
        for (int v = 0; v < 3; v++) {
            int wq = w + 1 - v;
            if (wq < 0 || wq >= WN) continue;
            acc += g_Z[((size_t)b * HWN + hq * WN + wq) * 576 + c * 9 + u * 3 + v];
        }
    }
    out[i] = x[i] + 0.25f * acc;
}

// ---------------- launch ----------------
extern "C" void kernel_launch(void* const* d_in, const int* in_sizes, int n_in,
                              void* d_out, int out_size) {
    const float* x    = (const float*)d_in[0];
    const float* w_mb = (const float*)d_in[1];
    const float* b_mb = (const float*)d_in[2];
    const float* a_mb = (const float*)d_in[3];
    const float* w_m  = (const float*)d_in[4];
    const float* b_m  = (const float*)d_in[5];
    const float* a_m  = (const float*)d_in[6];
    const float* w_a  = (const float*)d_in[7];
    const float* b_a  = (const float*)d_in[8];
    const float* a_a  = (const float*)d_in[9];
    const float* eps  = (const float*)d_in[10];
    float* out = (float*)d_out;

    k_copy_ref0<<<(BN * CN * HWN + 255) / 256, 256>>>(x);
    k_resize<<<dim3(1849, 4), 256>>>(x);
    k_conv_me<<<dim3(36, BN * 5), 256>>>(w_m, b_m, a_m, w_a, b_a, a_a);
    k_conv_mb<<<dim3(36, BN), 256>>>(x, w_mb, b_mb, a_mb);
    k_build_q<<<BN * HWN, 288>>>();
    k_build_k<<<BN * LTOT, 288>>>(eps);
    k_build_vt<<<dim3(576, BN), 256>>>();
    k_gemm_qk<<<dim3((LTOT + 127) / 128, HWN / 128, BN), 256>>>();
    k_softmax<<<BN * HWN, 256>>>();
    k_gemm_av<<<dim3((576 + 127) / 128, HWN / 128, BN), 256>>>();
    k_combine<<<(BN * CN * HWN + 255) / 256, 256>>>(x, out);
}

// round 6
// speedup vs baseline: 5.3770x; 1.2504x over previous
#include <cuda_runtime.h>
#include <cuda_fp16.h>
#include <math.h>
#include <stdint.h>

#define BN 4
#define CN 64
#define C2N 32
#define HN 48
#define WN 48
#define HWN 2304
#define LTOT 7470
#define KC1 576          // QK gemm K (2-term split: [Qh|Ql] . [Kh|Kh])
#define SPAD 7680        // score col stride
#define LP2 7488         // padded L for AV gemm (117 chunks of 64)

__constant__ int    c_HS[5]   = {48, 43, 38, 33, 28};
__constant__ int    c_LS[5]   = {2304, 1849, 1444, 1089, 784};
__constant__ int    c_LOFF[5] = {0, 2304, 4153, 5597, 6686};
__constant__ double c_SC[5]   = {1.0, 0.9, 0.8, 0.7, 0.6};

// ---------------- scratch ----------------
__device__ float g_ref[(size_t)BN * CN * LTOT];
__device__ float g_m  [(size_t)BN * C2N * LTOT];
__device__ float g_e  [(size_t)BN * CN * LTOT];
__device__ float g_mb [(size_t)BN * C2N * HWN];
__device__ __align__(16) __half g_Qc [(size_t)BN * HWN * KC1];   // [Qh|Ql]
__device__ __align__(16) __half g_Kc [(size_t)BN * LTOT * KC1];  // [Kh|Kh]
__device__ __align__(16) __half g_V16[(size_t)BN * 576 * LP2];   // V^T fp16
__device__ __align__(16) __half g_A16[(size_t)BN * HWN * LP2];   // attn fp16
__device__ __align__(16) float g_S[(size_t)BN * HWN * SPAD];     // raw scores fp32
__device__ __align__(16) float g_Z[(size_t)BN * HWN * 576];

// ---------------- ptx helpers ----------------
__device__ __forceinline__ uint32_t smem_u32(const void* p) {
    uint32_t a;
    asm("{ .reg .u64 t; cvta.to.shared.u64 t, %1; cvt.u32.u64 %0, t; }" : "=r"(a) : "l"(p));
    return a;
}
__device__ __forceinline__ void cp16(uint32_t d, const void* s, int sz) {
    asm volatile("cp.async.cg.shared.global [%0], [%1], 16, %2;"
                 :: "r"(d), "l"(s), "r"(sz) : "memory");
}
__device__ __forceinline__ void cp_commit() {
    asm volatile("cp.async.commit_group;" ::: "memory");
}
template <int N_>
__device__ __forceinline__ void cp_wait() {
    asm volatile("cp.async.wait_group %0;" :: "n"(N_) : "memory");
}
__device__ __forceinline__ void ldsm4(uint32_t* r, uint32_t addr) {
    asm volatile("ldmatrix.sync.aligned.m8n8.x4.shared.b16 {%0,%1,%2,%3}, [%4];"
        : "=r"(r[0]), "=r"(r[1]), "=r"(r[2]), "=r"(r[3]) : "r"(addr));
}
__device__ __forceinline__ void mma16816(float* c, const uint32_t* a, uint32_t b0, uint32_t b1) {
    asm volatile("mma.sync.aligned.m16n8k16.row.col.f32.f16.f16.f32 "
        "{%0,%1,%2,%3}, {%4,%5,%6,%7}, {%8,%9}, {%0,%1,%2,%3};"
        : "+f"(c[0]), "+f"(c[1]), "+f"(c[2]), "+f"(c[3])
        : "r"(a[0]), "r"(a[1]), "r"(a[2]), "r"(a[3]), "r"(b0), "r"(b1));
}
__device__ __forceinline__ void split_h(float v, __half& h, __half& l) {
    h = __float2half_rn(v);
    l = __float2half_rn(v - __half2float(h));
}

// ---------------- bicubic ----------------
__device__ __forceinline__ float cubicw(float t) {
    const float A = -0.75f;
    if (t <= 1.f) return ((A + 2.f) * t - (A + 3.f)) * t * t + 1.f;
    if (t <  2.f) return (((t - 5.f) * t + 8.f) * t - 4.f) * A;
    return 0.f;
}

__global__ void k_copy_ref0(const float* __restrict__ x) {
    int i = blockIdx.x * blockDim.x + threadIdx.x;
    if (i >= BN * CN * HWN) return;
    int b = i / (CN * HWN), r = i % (CN * HWN);
    g_ref[(size_t)b * CN * LTOT + r] = x[i];
}

__global__ void k_resize(const float* __restrict__ x) {
    int s  = blockIdx.y + 1;
    int hs = c_HS[s];
    int ls = hs * hs;
    int i  = blockIdx.x * blockDim.x + threadIdx.x;
    if (i >= BN * CN * ls) return;
    int b = i / (CN * ls), r = i % (CN * ls);
    int c = r / ls, p = r % ls;
    int oy = p / hs, ox = p % hs;
    double sc = c_SC[s];
    double syd = (oy + 0.5) / sc - 0.5;
    int   fy = (int)floor(syd);
    float fry = (float)(syd - fy);
    double sxd = (ox + 0.5) / sc - 0.5;
    int   fx = (int)floor(sxd);
    float frx = (float)(sxd - fx);
    float wy[4], wx[4]; int iy[4], ix[4];
#pragma unroll
    for (int k = 0; k < 4; k++) {
        wy[k] = cubicw(fabsf((float)(k - 1) - fry));
        int t = fy + k - 1; iy[k] = min(max(t, 0), HN - 1);
        wx[k] = cubicw(fabsf((float)(k - 1) - frx));
        t = fx + k - 1; ix[k] = min(max(t, 0), WN - 1);
    }
    const float* xp = x + ((size_t)b * CN + c) * HWN;
    float acc = 0.f;
#pragma unroll
    for (int ky = 0; ky < 4; ky++) {
        float ra = 0.f;
#pragma unroll
        for (int kx = 0; kx < 4; kx++) ra += wx[kx] * xp[iy[ky] * WN + ix[kx]];
        acc += wy[ky] * ra;
    }
    g_ref[(size_t)b * CN * LTOT + (size_t)c_LOFF[s] * CN + (size_t)c * ls + p] = acc;
}

// ---------------- 1x1 convs + PReLU ----------------
#define TPX 64
__global__ void k_conv_me(const float* __restrict__ w_m, const float* __restrict__ b_m,
                          const float* __restrict__ a_m, const float* __restrict__ w_a,
                          const float* __restrict__ b_a, const float* __restrict__ a_a) {
    int bs = blockIdx.y;
    int b = bs / 5, s = bs % 5;
    int ls = c_LS[s];
    int p0 = blockIdx.x * TPX;
    if (p0 >= ls) return;
    __shared__ float ws[96 * 64];
    __shared__ float bsm[96];
    __shared__ float intile[64][TPX];
    int tid = threadIdx.x;
    for (int i = tid; i < 32 * 64; i += 256) ws[i] = w_m[i];
    for (int i = tid; i < 64 * 64; i += 256) ws[32 * 64 + i] = w_a[i];
    if (tid < 32) bsm[tid] = b_m[tid];
    else if (tid < 96) bsm[tid] = b_a[tid - 32];
    float alm = *a_m, ala = *a_a;
    const float* inb = g_ref + (size_t)b * CN * LTOT + (size_t)c_LOFF[s] * CN;
    for (int i = tid; i < 64 * TPX; i += 256) {
        int c = i / TPX, p = i % TPX;
        intile[c][p] = (p0 + p < ls) ? inb[(size_t)c * ls + p0 + p] : 0.f;
    }
    __syncthreads();
    float* outm = g_m + (size_t)b * C2N * LTOT + (size_t)c_LOFF[s] * C2N;
    float* oute = g_e + (size_t)b * CN * LTOT + (size_t)c_LOFF[s] * CN;
#pragma unroll
    for (int j = 0; j < (96 * TPX) / 256; j++) {
        int pi = tid + 256 * j;
        int o = pi / TPX, p = pi % TPX;
        float acc = bsm[o];
        const float* wr = ws + o * 64;
#pragma unroll
        for (int c = 0; c < 64; c++) acc += wr[c] * intile[c][p];
        float al = (o < 32) ? alm : ala;
        float v = acc >= 0.f ? acc : al * acc;
        if (p0 + p < ls) {
            if (o < 32) outm[(size_t)o * ls + p0 + p] = v;
            else        oute[(size_t)(o - 32) * ls + p0 + p] = v;
        }
    }
}

__global__ void k_conv_mb(const float* __restrict__ x, const float* __restrict__ w,
                          const float* __restrict__ bias, const float* __restrict__ alpha) {
    int b = blockIdx.y;
    int p0 = blockIdx.x * TPX;
    __shared__ float ws[32 * 64];
    __shared__ float bsm[32];
    __shared__ float intile[64][TPX];
    int tid = threadIdx.x;
    for (int i = tid; i < 2048; i += 256) ws[i] = w[i];
    if (tid < 32) bsm[tid] = bias[tid];
    float al = *alpha;
    const float* inb = x + (size_t)b * CN * HWN;
    for (int i = tid; i < 64 * TPX; i += 256) {
        int c = i / TPX, p = i % TPX;
        intile[c][p] = inb[(size_t)c * HWN + p0 + p];
    }
    __syncthreads();
#pragma unroll
    for (int j = 0; j < (32 * TPX) / 256; j++) {
        int pi = tid + 256 * j;
        int o = pi / TPX, p = pi % TPX;
        float acc = bsm[o];
        const float* wr = ws + o * 64;
#pragma unroll
        for (int c = 0; c < 64; c++) acc += wr[c] * intile[c][p];
        g_mb[((size_t)b * C2N + o) * HWN + p0 + p] = acc >= 0.f ? acc : al * acc;
    }
}

// ---------------- builders ----------------
__global__ void k_build_q() {
    int bq = blockIdx.x;
    int b = bq / HWN, q = bq % HWN;
    int j = threadIdx.x;          // 288
    int c = j / 9, u = (j % 9) / 3, v = j % 3;
    int h = q / WN, w = q % WN;
    int hh = h + u - 1, ww = w + v - 1;
    float val = 0.f;
    if (hh >= 0 && hh < HN && ww >= 0 && ww < WN)
        val = g_mb[((size_t)b * C2N + c) * HWN + hh * WN + ww];
    __half hi, lo;
    split_h(val, hi, lo);
    size_t base = ((size_t)b * HWN + q) * KC1;
    g_Qc[base + j]       = hi;
    g_Qc[base + 288 + j] = lo;
}

__global__ void k_build_k(const float* __restrict__ eps_p) {
    int bl = blockIdx.x;
    int b = bl / LTOT, l = bl % LTOT;
    int s = 0;
#pragma unroll
    for (int t = 1; t < 5; t++) if (l >= c_LOFF[t]) s = t;
    int hs = c_HS[s], ls = c_LS[s];
    int p = l - c_LOFF[s];
    int y = p / hs, xx = p % hs;
    int j = threadIdx.x;          // 288
    int c = j / 9, u = (j % 9) / 3, v = j % 3;
    int yy = y + u - 1, x2 = xx + v - 1;
    float val = 0.f;
    if (yy >= 0 && yy < hs && x2 >= 0 && x2 < hs)
        val = g_m[(size_t)b * C2N * LTOT + (size_t)c_LOFF[s] * C2N + (size_t)c * ls + yy * hs + x2];
    __shared__ float red[512];
    red[j] = val * val;
    if (j < 224) red[288 + j] = 0.f;
    __syncthreads();
    for (int st = 256; st > 0; st >>= 1) {
        if (j < st) red[j] += red[j + st];
        __syncthreads();
    }
    float inv = 1.f / fmaxf(sqrtf(red[0]), *eps_p);
    __half hi = __float2half_rn(val * inv);
    size_t base = ((size_t)b * LTOT + l) * KC1;
    g_Kc[base + j]       = hi;
    g_Kc[base + 288 + j] = hi;
}

__global__ void k_build_vt() {
    int j = blockIdx.x;           // 0..575 (channel-tap)
    int b = blockIdx.y;
    int c = j / 9, u = (j % 9) / 3, v = j % 3;
    size_t obase = ((size_t)b * 576 + j) * LP2;
    for (int l = threadIdx.x; l < LP2; l += blockDim.x) {
        float val = 0.f;
        if (l < LTOT) {
            int s = 0;
            if (l >= c_LOFF[4]) s = 4;
            else if (l >= c_LOFF[3]) s = 3;
            else if (l >= c_LOFF[2]) s = 2;
            else if (l >= c_LOFF[1]) s = 1;
            int hs = c_HS[s], ls = c_LS[s];
            int p = l - c_LOFF[s];
            int y = p / hs, xx = p % hs;
            int yy = y + u - 1, x2 = xx + v - 1;
            if (yy >= 0 && yy < hs && x2 >= 0 && x2 < hs)
                val = g_e[(size_t)b * CN * LTOT + (size_t)c_LOFF[s] * CN + (size_t)c * ls + yy * hs + x2];
        }
        g_V16[obase + l] = __float2half_rn(val);
    }
}

// ---------------- HMMA GEMM: C[M,N] = A[M,K] * B[N,K]^T ----------------
// block 128x128x64, 8 warps (warp tile 64x32), double-buffered cp.async,
// 144B smem rows (conflict-free: 36 banks/row = 4 mod 32), fp32 accum.
#define SMB 73728   // 4 tiles x 18432 B
__device__ __forceinline__ void hgemm_dev(const __half* __restrict__ A,
                                          const __half* __restrict__ B,
                                          float* __restrict__ C,
                                          int N, int K, int lda, int ldb, int ldc) {
    extern __shared__ __align__(16) char sh[];
    int tid = threadIdx.x, lane = tid & 31, w = tid >> 5;
    int wm = w >> 2, wn = w & 3;                  // warp grid 2(M) x 4(N)
    int m0 = blockIdx.y * 128, n0 = blockIdx.x * 128;

    const __half* Ab = A + (size_t)m0 * lda;
    uint32_t s0 = smem_u32(sh);

    float c[4][4][4];
#pragma unroll
    for (int i = 0; i < 4; i++)
#pragma unroll
        for (int j = 0; j < 4; j++)
#pragma unroll
            for (int q = 0; q < 4; q++) c[i][j][q] = 0.f;

    int r_ = tid >> 3, g = tid & 7;    // load row(0..31) / 16B-group(0..7)
    int NC = K >> 6;

    auto issue = [&](int ch, int buf) {
        int k0 = ch << 6;
        uint32_t ab = s0 + buf * 36864;
        uint32_t bb = ab + 18432;
#pragma unroll
        for (int it = 0; it < 4; ++it) {
            int rr = r_ + it * 32;
            cp16(ab + rr * 144 + g * 16, Ab + (size_t)rr * lda + k0 + g * 8, 16);
            int n = n0 + rr;
            cp16(bb + rr * 144 + g * 16, B + (size_t)n * ldb + k0 + g * 8,
                 (n < N) ? 16 : 0);
        }
        cp_commit();
    };

    issue(0, 0);
    for (int ch = 0; ch < NC; ++ch) {
        int buf = ch & 1;
        if (ch + 1 < NC) { issue(ch + 1, buf ^ 1); cp_wait<1>(); }
        else             { cp_wait<0>(); }
        __syncthreads();

        uint32_t abase = s0 + buf * 36864;
        uint32_t bbase = abase + 18432;
        int lr = lane & 15, lh = lane >> 4;
#pragma unroll
        for (int ks = 0; ks < 4; ++ks) {
            uint32_t af[4][4], bf[2][4];
#pragma unroll
            for (int ms = 0; ms < 4; ++ms)
                ldsm4(af[ms], abase + (wm * 64 + ms * 16 + lr) * 144 + ks * 32 + lh * 16);
#pragma unroll
            for (int ns = 0; ns < 2; ++ns)
                ldsm4(bf[ns], bbase + (wn * 32 + ns * 16 + lr) * 144 + ks * 32 + lh * 16);
#pragma unroll
            for (int ms = 0; ms < 4; ++ms)
#pragma unroll
                for (int j = 0; j < 4; ++j)
                    mma16816(c[ms][j], af[ms], bf[j >> 1][j & 1], bf[j >> 1][2 + (j & 1)]);
        }
        __syncthreads();
    }

    // epilogue
#pragma unroll
    for (int ms = 0; ms < 4; ++ms) {
#pragma unroll
        for (int j = 0; j < 4; ++j) {
            int row = m0 + wm * 64 + ms * 16 + (lane >> 2);
            int col = n0 + wn * 32 + j * 8 + 2 * (lane & 3);
            if (col < N) {
                *(float2*)&C[(size_t)row * ldc + col] = make_float2(c[ms][j][0], c[ms][j][1]);
                *(float2*)&C[(size_t)(row + 8) * ldc + col] = make_float2(c[ms][j][2], c[ms][j][3]);
            }
        }
    }
}

__global__ __launch_bounds__(256) void k_gemm_qk() {
    int b = blockIdx.z;
    hgemm_dev(g_Qc + (size_t)b * HWN * KC1,
              g_Kc + (size_t)b * LTOT * KC1,
              g_S  + (size_t)b * HWN * SPAD,
              LTOT, KC1, KC1, KC1, SPAD);
}

__global__ __launch_bounds__(256) void k_gemm_av() {
    int b = blockIdx.z;
    hgemm_dev(g_A16 + (size_t)b * HWN * LP2,
              g_V16 + (size_t)b * 576 * LP2,
              g_Z   + (size_t)b * HWN * 576,
              576, LP2, LP2, LP2, 576);
}

// ---------------- softmax: S -> fp16 attn ----------------
__global__ __launch_bounds__(256) void k_softmax() {
    size_t row = blockIdx.x;
    const float* ptr = g_S + row * SPAD;
    __half* op = g_A16 + row * LP2;
    int tid = threadIdx.x;
    float v[30];
    float mx = -1e30f;
#pragma unroll
    for (int i = 0; i < 30; i++) {
        int idx = tid + i * 256;
        v[i] = (idx < LTOT) ? ptr[idx] : -1e30f;
        mx = fmaxf(mx, v[i]);
    }
    __shared__ float red[256];
    red[tid] = mx;
    __syncthreads();
    for (int st = 128; st > 0; st >>= 1) {
        if (tid < st) red[tid] = fmaxf(red[tid], red[tid + st]);
        __syncthreads();
    }
    mx = red[0];
    __syncthreads();
    float sum = 0.f;
#pragma unroll
    for (int i = 0; i < 30; i++) {
        int idx = tid + i * 256;
        if (idx < LTOT) {
            v[i] = __expf(10.f * (v[i] - mx));
            sum += v[i];
        }
    }
    red[tid] = sum;
    __syncthreads();
    for (int st = 128; st > 0; st >>= 1) {
        if (tid < st) red[tid] += red[tid + st];
        __syncthreads();
    }
    float inv = 1.f / red[0];
#pragma unroll
    for (int i = 0; i < 30; i++) {
        int idx = tid + i * 256;
        if (idx < LTOT) op[idx] = __float2half_rn(v[i] * inv);
        else if (idx < LP2) op[idx] = __float2half_rn(0.f);
    }
}

// ---------------- combine ----------------
__global__ void k_combine(const float* __restrict__ x, float* __restrict__ out) {
    int i = blockIdx.x * blockDim.x + threadIdx.x;
    if (i >= BN * CN * HWN) return;
    int b = i / (CN * HWN), r = i % (CN * HWN);
    int c = r / HWN, p = r % HWN;
    int h = p / WN, w = p % WN;
    float acc = 0.f;
#pragma unroll
    for (int u = 0; u < 3; u++) {
        int hq = h + 1 - u;
        if (hq < 0 || hq >= HN) continue;
#pragma unroll
        for (int v = 0; v < 3; v++) {
            int wq = w + 1 - v;
            if (wq < 0 || wq >= WN) continue;
            acc += g_Z[((size_t)b * HWN + hq * WN + wq) * 576 + c * 9 + u * 3 + v];
        }
    }
    out[i] = x[i] + 0.25f * acc;
}

// ---------------- launch ----------------
extern "C" void kernel_launch(void* const* d_in, const int* in_sizes, int n_in,
                              void* d_out, int out_size) {
    const float* x    = (const float*)d_in[0];
    const float* w_mb = (const float*)d_in[1];
    const float* b_mb = (const float*)d_in[2];
    const float* a_mb = (const float*)d_in[3];
    const float* w_m  = (const float*)d_in[4];
    const float* b_m  = (const float*)d_in[5];
    const float* a_m  = (const float*)d_in[6];
    const float* w_a  = (const float*)d_in[7];
    const float* b_a  = (const float*)d_in[8];
    const float* a_a  = (const float*)d_in[9];
    const float* eps  = (const float*)d_in[10];
    float* out = (float*)d_out;

    cudaFuncSetAttribute(k_gemm_qk, cudaFuncAttributeMaxDynamicSharedMemorySize, SMB);
    cudaFuncSetAttribute(k_gemm_av, cudaFuncAttributeMaxDynamicSharedMemorySize, SMB);

    k_copy_ref0<<<(BN * CN * HWN + 255) / 256, 256>>>(x);
    k_resize<<<dim3(1849, 4), 256>>>(x);
    k_conv_me<<<dim3(36, BN * 5), 256>>>(w_m, b_m, a_m, w_a, b_a, a_a);
    k_conv_mb<<<dim3(36, BN), 256>>>(x, w_mb, b_mb, a_mb);
    k_build_q<<<BN * HWN, 288>>>();
    k_build_k<<<BN * LTOT, 288>>>(eps);
    k_build_vt<<<dim3(576, BN), 256>>>();
    k_gemm_qk<<<dim3((LTOT + 127) / 128, HWN / 128, BN), 256, SMB>>>();
    k_softmax<<<BN * HWN, 256>>>();
    k_gemm_av<<<dim3((576 + 127) / 128, HWN / 128, BN), 256, SMB>>>();
    k_combine<<<(BN * CN * HWN + 255) / 256, 256>>>(x, out);
}